// round 11
// baseline (speedup 1.0000x reference)
#include <cuda_runtime.h>

// MedianFilterLoss, decomposed:
//   loss = sum_i softplus((1-2*t_i)*x_i)                       (base, elementwise)
//        - sum_{runs of ones, len>=3} max-weight subset of w_i = relu(-x_i)
//          with pairwise distance >= 3 (3-state max-plus DP per run)
// Warp-autonomous 1024-element tiles: no block-wide barrier between the load
// phase and the DP phase, so memory and compute phases of different warps mix.
// Staging: element = relu(-x) if t==1, else -1.0 sentinel (fp32, warp smem).
// DP reset = -0.0f; "len>=3" == sign(m0) >= 0. Prefix runs: close suppressed.

#define T_LEN 16384
#define TILE  8192
#define NTH   256
#define WTILE 1024        // elements per warp
#define LROW  36          // floats per lane row (32 data + 4 pad) — 16B aligned
#define NEGZ  __int_as_float(0x80000000)
#define LN2F  0.6931471805599453f

__device__ float g_partial[2048];
__device__ unsigned int g_done;

__global__ void __launch_bounds__(NTH, 5) mfl_fused(const float* __restrict__ xg,
                                                    const int* __restrict__ tg,
                                                    float* __restrict__ o,
                                                    double inv_n) {
    __shared__ float swf[NTH / 32][32 * LROW];   // 8 x 4608B
    __shared__ float wsum[NTH / 32];
    __shared__ double sdbl[NTH];
    __shared__ unsigned int s_last;

    const int bid  = blockIdx.x;
    const int row  = bid >> 1;
    const int half = bid & 1;
    const int tid  = threadIdx.x;
    const int lane = tid & 31;
    const int wid  = tid >> 5;
    const int gbase  = row * T_LEN + half * TILE + wid * WTILE;
    const int wti    = half * 8 + wid;           // warp-tile index within row (0..15)
    const int rowend = row * T_LEN + T_LEN;

    // early prefetch of previous target bit (lane 0 only)
    int prevt = 0;
    if (lane == 0 && wti != 0) prevt = tg[gbase - 1];

    // ---- Phase 1: warp-local coalesced loads; base loss; staging ----
    float accR = 0.0f, accL = 0.0f;
    const float4* xv = reinterpret_cast<const float4*>(xg + gbase);
    const int4*   tv = reinterpret_cast<const int4*>(tg + gbase);
    float* ws = swf[wid];
#pragma unroll
    for (int mb = 0; mb < 2; ++mb) {
        float4 vx[4];
        int4   vt[4];
#pragma unroll
        for (int q = 0; q < 4; ++q) {
            int i = (mb * 4 + q) * 32 + lane;
            vx[q] = xv[i];
            vt[q] = tv[i];
        }
#pragma unroll
        for (int q = 0; q < 4; ++q) {
            int e0 = ((mb * 4 + q) * 32 + lane) * 4;      // tile-relative
            float xs[4] = {vx[q].x, vx[q].y, vx[q].z, vx[q].w};
            int   ts[4] = {vt[q].x, vt[q].y, vt[q].z, vt[q].w};
            float enc[4];
#pragma unroll
            for (int j = 0; j < 4; ++j) {
                float x  = xs[j];
                bool one = (ts[j] != 0);
                float u  = exp2f(fabsf(x) * -1.4426950408889634f);
                accL    += __log2f(1.0f + u);
                float s  = one ? -x : x;
                float w  = fmaxf(s, 0.0f);
                accR    += w;
                enc[j]   = one ? w : -1.0f;
            }
            int oo = e0 >> 5, cc = e0 & 31;               // aligned conflict-free STS.128
            float4 st = {enc[0], enc[1], enc[2], enc[3]};
            *reinterpret_cast<float4*>(&ws[oo * LROW + cc]) = st;
        }
    }
    float acc = accR;
    __syncwarp();

    // ---- Phase 2: convergent per-lane DP over 32 contiguous elements ----
    bool suppress = lane ? (ws[(lane - 1) * LROW + 31] >= 0.0f) : (prevt != 0);
    float m0 = NEGZ, m1 = NEGZ, m2 = NEGZ;
    bool b = false;
    const float* mine = &ws[lane * LROW];
#pragma unroll
    for (int c = 0; c < 8; ++c) {                         // 8 x LDS.128
        float4 q = *reinterpret_cast<const float4*>(mine + c * 4);
        float fv[4] = {q.x, q.y, q.z, q.w};
#pragma unroll
        for (int e = 0; e < 4; ++e) {
            float f = fv[e];
            b = (f >= 0.0f);
            bool doclose = !b && !suppress && (__float_as_int(m0) >= 0);
            if (doclose) acc -= m2;
            suppress = suppress && b;
            float nm2 = fabsf(fmaxf(m2, m0 + f));
            m0 = b ? m1 : NEGZ;
            m1 = b ? m2 : NEGZ;
            m2 = b ? nm2 : NEGZ;
        }
    }

    // ---- suffix: open run at chunk end ----
    if (b && !suppress) {
        bool alive = true;
        if (lane < 31) {
            // 8-element overlap into next lane's region (warp smem)
            const float* nb = &ws[(lane + 1) * LROW];
#pragma unroll
            for (int c = 0; c < 2; ++c) {
                float4 q = *reinterpret_cast<const float4*>(nb + c * 4);
                float fv[4] = {q.x, q.y, q.z, q.w};
#pragma unroll
                for (int e = 0; e < 4; ++e) {
                    float f = fv[e];
                    bool cont = alive && (f >= 0.0f);
                    bool cls  = alive && !cont && (__float_as_int(m0) >= 0);
                    if (cls) acc -= m2;
                    float nm2 = fabsf(fmaxf(m2, m0 + f));
                    m0 = cont ? m1 : m0;
                    m1 = cont ? m2 : m1;
                    m2 = cont ? nm2 : m2;
                    alive = cont;
                }
            }
            if (alive) {                                  // very rare: walk warp smem
                int q = (lane + 1) * 32 + 8;
                while (q < WTILE) {
                    float f = ws[(q >> 5) * LROW + (q & 31)];
                    if (f < 0.0f) break;
                    float nm2 = fabsf(fmaxf(m2, m0 + f));
                    m0 = m1; m1 = m2; m2 = nm2; ++q;
                }
                if (q < WTILE) {                          // closed at a zero
                    if (__float_as_int(m0) >= 0) acc -= m2;
                    alive = false;
                }
            }
        }
        if (alive) {                                      // continue past warp tile
            int g = gbase + WTILE;
            if (lane == 31 && g < rowend) {               // batched 8-elem overlap
                const int4*   tp = reinterpret_cast<const int4*>(tg + g);
                const float4* xp = reinterpret_cast<const float4*>(xg + g);
                int4   ta = tp[0], tb = tp[1];
                float4 xa = xp[0], xb = xp[1];
                int   tt[8] = {ta.x, ta.y, ta.z, ta.w, tb.x, tb.y, tb.z, tb.w};
                float xx[8] = {xa.x, xa.y, xa.z, xa.w, xb.x, xb.y, xb.z, xb.w};
#pragma unroll
                for (int e = 0; e < 8; ++e) {
                    float f = (tt[e] != 0) ? fmaxf(-xx[e], 0.0f) : -1.0f;
                    bool cont = alive && (f >= 0.0f);
                    bool cls  = alive && !cont && (__float_as_int(m0) >= 0);
                    if (cls) acc -= m2;
                    float nm2 = fabsf(fmaxf(m2, m0 + f));
                    m0 = cont ? m1 : m0;
                    m1 = cont ? m2 : m1;
                    m2 = cont ? nm2 : m2;
                    alive = cont;
                }
                g += 8;
            }
            if (alive) {                                  // rare serial global tail
                while (g < rowend && tg[g] != 0) {
                    float w = fmaxf(-xg[g], 0.0f);
                    float nm2 = fabsf(fmaxf(m2, m0 + w));
                    m0 = m1; m1 = m2; m2 = nm2; ++g;
                }
                if (__float_as_int(m0) >= 0) acc -= m2;   // close at zero / row end
            }
        }
    }

    acc = fmaf(accL, LN2F, acc);

    // ---- block reduction ----
#pragma unroll
    for (int off = 16; off; off >>= 1)
        acc += __shfl_down_sync(0xFFFFFFFFu, acc, off);
    if (lane == 0) wsum[wid] = acc;
    __syncthreads();
    float blocksum = 0.0f;
    if (wid == 0) {
        float v = (lane < NTH / 32) ? wsum[lane] : 0.0f;
#pragma unroll
        for (int off = 4; off; off >>= 1)
            v += __shfl_down_sync(0xFFFFFFFFu, v, off);
        blocksum = v;
    }

    // ---- last-block-done final reduction (single launch) ----
    if (tid == 0) {
        g_partial[bid] = blocksum;
        __threadfence();
        unsigned old = atomicAdd(&g_done, 1u);
        s_last = (old == gridDim.x - 1) ? 1u : 0u;
    }
    __syncthreads();
    if (s_last) {
        const volatile float* gp = g_partial;
        double sv = 0.0;
        for (int i = tid; i < (int)gridDim.x; i += NTH)
            sv += (double)gp[i];
        sdbl[tid] = sv;
        __syncthreads();
#pragma unroll
        for (int off = NTH / 2; off; off >>= 1) {
            if (tid < off) sdbl[tid] += sdbl[tid + off];
            __syncthreads();
        }
        if (tid == 0) {
            o[0] = (float)(sdbl[0] * inv_n);
            g_done = 0;                                   // reset for next replay
        }
    }
}

extern "C" void kernel_launch(void* const* d_in, const int* in_sizes, int n_in,
                              void* d_out, int out_size) {
    const float* xg = (const float*)d_in[0];
    const int*   tg = (const int*)d_in[1];
    long long n = (long long)in_sizes[0];      // 1024 * 16384
    int grid = (int)(n / TILE);                // 2048
    mfl_fused<<<grid, NTH>>>(xg, tg, (float*)d_out, 1.0 / (double)n);
}

// round 13
// speedup vs baseline: 1.0771x; 1.0771x over previous
#include <cuda_runtime.h>

// MedianFilterLoss, decomposed:
//   loss = sum_i softplus((1-2*t_i)*x_i)                       (base, elementwise)
//        - sum_{runs of ones, len>=3} max-weight subset of w_i = relu(-x_i)
//          with pairwise distance >= 3 (3-state max-plus DP per run)
// Persistent single-wave grid (148*5 CTAs): each CTA loops over ~3 tiles,
// eliminating ~13 wave transitions of the 2048-CTA launch.
// Float staging in smem: element = relu(-x) if t==1, else -1.0 sentinel.
// DP reset = -0.0f; "len>=3" == sign(m0)>=0. Prefix runs: close suppressed.

#define T_LEN 16384
#define TILE  8192
#define NTH   256
#define EPT   32
#define ROWF  36          // floats per thread-row (32 data + 4 pad) = 144B
#define NTILES 2048
#define GRID  740         // 148 SMs * 5 CTAs
#define NEGZ  __int_as_float(0x80000000)
#define LN2F  0.6931471805599453f

__device__ float g_partial[2048];
__device__ unsigned int g_done;

__global__ void __launch_bounds__(NTH, 5) mfl_fused(const float* __restrict__ xg,
                                                    const int* __restrict__ tg,
                                                    float* __restrict__ o,
                                                    double inv_n) {
    __shared__ float swf[NTH * ROWF];
    __shared__ float wsum[NTH / 32];
    __shared__ double sdbl[NTH];
    __shared__ unsigned int s_last;

    const int tid  = threadIdx.x;
    const int lane = tid & 31;
    const int wid  = tid >> 5;

    float acc  = 0.0f;    // relu terms + DP corrections
    float accL = 0.0f;    // log2 terms, * ln2 at the end

    for (int tile = blockIdx.x; tile < NTILES; tile += gridDim.x) {
        const int row  = tile >> 1;
        const int half = tile & 1;
        const int base = row * T_LEN + half * TILE;

        __syncthreads();                          // smem safe to overwrite

        // ---- Phase 1: macro-batched coalesced loads; base loss; staging ----
        const float4* xv = reinterpret_cast<const float4*>(xg + base);
        const int4*   tv = reinterpret_cast<const int4*>(tg + base);
#pragma unroll
        for (int mb = 0; mb < 2; ++mb) {
            float4 vx[4];
            int4   vt[4];
#pragma unroll
            for (int q = 0; q < 4; ++q) {
                int i = (mb * 4 + q) * NTH + tid;
                vx[q] = xv[i];
                vt[q] = tv[i];
            }
#pragma unroll
            for (int q = 0; q < 4; ++q) {
                int i = (mb * 4 + q) * NTH + tid;
                float xs[4] = {vx[q].x, vx[q].y, vx[q].z, vx[q].w};
                int   ts[4] = {vt[q].x, vt[q].y, vt[q].z, vt[q].w};
                float enc[4];
#pragma unroll
                for (int j = 0; j < 4; ++j) {
                    float x  = xs[j];
                    bool one = (ts[j] != 0);
                    float u  = exp2f(fabsf(x) * -1.4426950408889634f);
                    accL    += __log2f(1.0f + u);
                    float s  = one ? -x : x;
                    float w  = fmaxf(s, 0.0f);
                    acc     += w;
                    enc[j]   = one ? w : -1.0f;
                }
                unsigned r2 = (unsigned)(i >> 3);
                unsigned c2 = (unsigned)(i & 7) * 4u;
                float4 st = {enc[0], enc[1], enc[2], enc[3]};
                *reinterpret_cast<float4*>(&swf[r2 * ROWF + c2]) = st;
            }
        }
        __syncthreads();

        // ---- Phase 2: convergent per-thread DP over 32 contiguous elements ----
        bool suppress;
        if (tid == 0) suppress = half ? (tg[base - 1] != 0) : false;
        else          suppress = (swf[(tid - 1) * ROWF + (EPT - 1)] >= 0.0f);

        float m0 = NEGZ, m1 = NEGZ, m2 = NEGZ;
        bool b = false;
        const float* mine = &swf[tid * ROWF];
#pragma unroll
        for (int c = 0; c < EPT / 4; ++c) {           // 8 x LDS.128
            float4 q = *reinterpret_cast<const float4*>(mine + c * 4);
            float fv[4] = {q.x, q.y, q.z, q.w};
#pragma unroll
            for (int e = 0; e < 4; ++e) {
                float f = fv[e];
                b = (f >= 0.0f);
                bool doclose = !b && !suppress && (__float_as_int(m0) >= 0);
                if (doclose) acc -= m2;
                suppress = suppress && b;
                float nm2 = fabsf(fmaxf(m2, m0 + f));
                m0 = b ? m1 : NEGZ;
                m1 = b ? m2 : NEGZ;
                m2 = b ? nm2 : NEGZ;
            }
        }

        // ---- suffix: open run at chunk end ----
        if (b && !suppress) {
            bool alive = true;
            if (tid < NTH - 1) {
                const float* nb = &swf[(tid + 1) * ROWF];
#pragma unroll
                for (int c = 0; c < 2; ++c) {
                    float4 q = *reinterpret_cast<const float4*>(nb + c * 4);
                    float fv[4] = {q.x, q.y, q.z, q.w};
#pragma unroll
                    for (int e = 0; e < 4; ++e) {
                        float f = fv[e];
                        bool cont = alive && (f >= 0.0f);
                        bool cls  = alive && !cont && (__float_as_int(m0) >= 0);
                        if (cls) acc -= m2;
                        float nm2 = fabsf(fmaxf(m2, m0 + f));
                        m0 = cont ? m1 : m0;
                        m1 = cont ? m2 : m1;
                        m2 = cont ? nm2 : m2;
                        alive = cont;
                    }
                }
            }
            if (alive) {                               // rare: run alive past +8
                int p = (tid + 1) * EPT + ((tid < NTH - 1) ? 8 : 0);
                while (p < TILE) {
                    float f = swf[(p >> 5) * ROWF + (p & 31)];
                    if (f < 0.0f) break;
                    float nm2 = fabsf(fmaxf(m2, m0 + f));
                    m0 = m1; m1 = m2; m2 = nm2; ++p;
                }
                if (p == TILE && half == 0) {          // spill across mid-row boundary
                    int g = base + TILE;
                    const int gend = row * T_LEN + T_LEN;
                    while (g < gend && tg[g] != 0) {
                        float w = fmaxf(-xg[g], 0.0f);
                        float nm2 = fabsf(fmaxf(m2, m0 + w));
                        m0 = m1; m1 = m2; m2 = nm2; ++g;
                    }
                }
                if (__float_as_int(m0) >= 0) acc -= m2; // close at zero / row end
            }
        }
    }

    acc = fmaf(accL, LN2F, acc);

    // ---- block reduction ----
#pragma unroll
    for (int off = 16; off; off >>= 1)
        acc += __shfl_down_sync(0xFFFFFFFFu, acc, off);
    if (lane == 0) wsum[wid] = acc;
    __syncthreads();
    float blocksum = 0.0f;
    if (wid == 0) {
        float v = (lane < NTH / 32) ? wsum[lane] : 0.0f;
#pragma unroll
        for (int off = 4; off; off >>= 1)
            v += __shfl_down_sync(0xFFFFFFFFu, v, off);
        blocksum = v;
    }

    // ---- last-block-done final reduction (single launch) ----
    if (tid == 0) {
        g_partial[blockIdx.x] = blocksum;
        __threadfence();
        unsigned old = atomicAdd(&g_done, 1u);
        s_last = (old == gridDim.x - 1) ? 1u : 0u;
    }
    __syncthreads();
    if (s_last) {
        const volatile float* gp = g_partial;
        double sv = 0.0;
        for (int i = tid; i < (int)gridDim.x; i += NTH)
            sv += (double)gp[i];
        sdbl[tid] = sv;
        __syncthreads();
#pragma unroll
        for (int off = NTH / 2; off; off >>= 1) {
            if (tid < off) sdbl[tid] += sdbl[tid + off];
            __syncthreads();
        }
        if (tid == 0) {
            o[0] = (float)(sdbl[0] * inv_n);
            g_done = 0;                                // reset for next graph replay
        }
    }
}

extern "C" void kernel_launch(void* const* d_in, const int* in_sizes, int n_in,
                              void* d_out, int out_size) {
    const float* xg = (const float*)d_in[0];
    const int*   tg = (const int*)d_in[1];
    long long n = (long long)in_sizes[0];      // 1024 * 16384
    mfl_fused<<<GRID, NTH>>>(xg, tg, (float*)d_out, 1.0 / (double)n);
}